// round 2
// baseline (speedup 1.0000x reference)
#include <cuda_runtime.h>
#include <cuda_bf16.h>
#include <mma.h>

using namespace nvcuda;

#define NROWS 2048
#define DIM   1024

// ---------------- scratch (__device__ globals; no allocations allowed) ----------------
__device__ __align__(256) __nv_bfloat16 g_h_bf  [NROWS*DIM];
__device__ __align__(256) __nv_bfloat16 g_p0_bf [1024*1024];
__device__ __align__(256) __nv_bfloat16 g_p1_bf [1024*256];
__device__ __align__(256) __nv_bfloat16 g_p2_bf [1024*64];
__device__ __align__(256) __nv_bfloat16 g_w0_bf [20000*1024];
__device__ __align__(256) __nv_bfloat16 g_w1_bf [30000*256];
__device__ __align__(256) __nv_bfloat16 g_w2_bf [50000*64];
__device__ __align__(256) float         g_hp0_f [NROWS*1024];
__device__ __align__(256) float         g_hp1_f [NROWS*256];
__device__ __align__(256) float         g_hp2_f [NROWS*64];
__device__ __align__(256) __nv_bfloat16 g_hp0_bf[NROWS*1024];
__device__ __align__(256) __nv_bfloat16 g_hp1_bf[NROWS*256];
__device__ __align__(256) __nv_bfloat16 g_hp2_bf[NROWS*64];
__device__ __align__(256) float g_sum0[NROWS];
__device__ __align__(256) float g_sum1[NROWS];
__device__ __align__(256) float g_sum2[NROWS];
__device__ __align__(256) float g_selh [NROWS];   // head logit at selected column
__device__ __align__(256) float g_selv1[NROWS];   // tail1 logit at target index
__device__ __align__(256) float g_selv2[NROWS];   // tail2 logit at target index
__device__ __align__(256) int   g_selc0[NROWS];
__device__ __align__(256) int   g_selc1[NROWS];
__device__ __align__(256) int   g_selc2[NROWS];
__device__ __align__(256) int   g_tgt  [NROWS];   // decoded int targets

// ---------------- fp32 -> bf16 conversion ----------------
__global__ void k_conv(__nv_bfloat16* __restrict__ dst, const float* __restrict__ src, int n) {
    int i = blockIdx.x * blockDim.x + threadIdx.x;
    int stride = gridDim.x * blockDim.x;
    for (; i < n; i += stride) dst[i] = __float2bfloat16(src[i]);
}

// ---------------- init (single block): detect target dtype, decode, zero accumulators ----
// JAX silently demotes int64 randint to int32 when x64 is disabled, so the target
// buffer may be int32 OR int64. Detection: look at the first NROWS int32 words
// (in-bounds for either dtype). If the data is int64 (values < 2^31, nonneg),
// every odd word is a zero high-half. If int32, the odd words are targets and
// ~all nonzero. Decode accordingly.
__global__ void k_init(const int* __restrict__ t32) {
    __shared__ int s_nonzero_odd;
    if (threadIdx.x == 0) s_nonzero_odd = 0;
    __syncthreads();
    for (int i = threadIdx.x; i < NROWS / 2; i += blockDim.x)
        if (t32[2 * i + 1] != 0) atomicOr(&s_nonzero_odd, 1);
    __syncthreads();
    bool is64 = (s_nonzero_odd == 0);
    for (int r = threadIdx.x; r < NROWS; r += blockDim.x) {
        int t = is64 ? t32[2 * r] : t32[r];
        g_tgt[r] = t;
        g_sum0[r] = 0.f; g_sum1[r] = 0.f; g_sum2[r] = 0.f;
        g_selc0[r] = (t < 20000) ? t : -1;
        int t1 = t - 20000; if (t1 < 0) t1 = 0; if (t1 > 29999) t1 = 29999;
        g_selc1[r] = t1;
        int t2 = t - 50000; if (t2 < 0) t2 = 0; if (t2 > 49999) t2 = 49999;
        g_selc2[r] = t2;
    }
}

// ---------------- bf16 wmma GEMM ----------------
// C[M,N] = A[M,K] * op(B)
//   BT=true : B is [N,K] row-major (i.e. C = A * B^T)         (head / tail GEMMs)
//   BT=false: B is [K,N] row-major (i.e. C = A * B)           (projection GEMMs)
// FUSE=true : no C written; per-row sum of exp(logit+bias) atomically added to
//             sumexp[row]; logit at column selc[row] captured into selv[row].
template<bool BT, bool FUSE>
__global__ void k_gemm(const __nv_bfloat16* __restrict__ A,
                       const __nv_bfloat16* __restrict__ B,
                       const float* __restrict__ bias,
                       float* __restrict__ C,
                       int N, int K,
                       const int* __restrict__ selc,
                       float* __restrict__ selv,
                       float* __restrict__ sumexp)
{
    constexpr int BM = 64, BN = 64, BK = 32;
    constexpr int SA  = BK + 8;   // 40 (80B rows, 16B aligned)
    constexpr int SBT = BK + 8;   // 40
    constexpr int SBN = BN + 8;   // 72

    __shared__ __nv_bfloat16 As[BM * SA];
    __shared__ __nv_bfloat16 Bs[BM * SA];        // fits both layouts (64*40 >= 32*72)
    __shared__ float Cs[BM][BN + 4];
    __shared__ float rs[BM][4];

    const int tid  = threadIdx.x;
    const int warp = tid >> 5;
    const int wm   = warp >> 1;     // 0..3 (M)
    const int wn   = warp & 1;      // 0..1 (N)
    const int bm   = blockIdx.y * BM;
    const int bn   = blockIdx.x * BN;

    wmma::fragment<wmma::accumulator, 16, 16, 16, float> acc[2];
    wmma::fill_fragment(acc[0], 0.f);
    wmma::fill_fragment(acc[1], 0.f);

    for (int k0 = 0; k0 < K; k0 += BK) {
        {
            int r = tid >> 2, q = tid & 3;
            const uint4* src = reinterpret_cast<const uint4*>(A + (size_t)(bm + r) * K + k0 + q * 8);
            *reinterpret_cast<uint4*>(&As[r * SA + q * 8]) = *src;
        }
        if constexpr (BT) {
            int r = tid >> 2, q = tid & 3;
            int gn = bn + r;
            uint4 v = make_uint4(0u, 0u, 0u, 0u);
            if (gn < N)
                v = *reinterpret_cast<const uint4*>(B + (size_t)gn * K + k0 + q * 8);
            *reinterpret_cast<uint4*>(&Bs[r * SBT + q * 8]) = v;
        } else {
            int r = tid >> 3, q = tid & 7;   // 32 k-rows x 64 n
            const uint4* src = reinterpret_cast<const uint4*>(B + (size_t)(k0 + r) * N + bn + q * 8);
            *reinterpret_cast<uint4*>(&Bs[r * SBN + q * 8]) = *src;
        }
        __syncthreads();

        #pragma unroll
        for (int kk = 0; kk < BK; kk += 16) {
            wmma::fragment<wmma::matrix_a, 16, 16, 16, __nv_bfloat16, wmma::row_major> af;
            wmma::load_matrix_sync(af, &As[(wm * 16) * SA + kk], SA);
            if constexpr (BT) {
                wmma::fragment<wmma::matrix_b, 16, 16, 16, __nv_bfloat16, wmma::col_major> bfr;
                #pragma unroll
                for (int j = 0; j < 2; j++) {
                    wmma::load_matrix_sync(bfr, &Bs[(wn * 32 + j * 16) * SBT + kk], SBT);
                    wmma::mma_sync(acc[j], af, bfr, acc[j]);
                }
            } else {
                wmma::fragment<wmma::matrix_b, 16, 16, 16, __nv_bfloat16, wmma::row_major> bfr;
                #pragma unroll
                for (int j = 0; j < 2; j++) {
                    wmma::load_matrix_sync(bfr, &Bs[kk * SBN + wn * 32 + j * 16], SBN);
                    wmma::mma_sync(acc[j], af, bfr, acc[j]);
                }
            }
        }
        __syncthreads();
    }

    if constexpr (!FUSE) {
        #pragma unroll
        for (int j = 0; j < 2; j++)
            wmma::store_matrix_sync(C + (size_t)(bm + wm * 16) * N + bn + wn * 32 + j * 16,
                                    acc[j], N, wmma::mem_row_major);
        return;
    } else {
        #pragma unroll
        for (int j = 0; j < 2; j++)
            wmma::store_matrix_sync(&Cs[wm * 16][wn * 32 + j * 16], acc[j], BN + 4,
                                    wmma::mem_row_major);
        __syncthreads();

        int r   = tid & 63;        // row within tile
        int seg = tid >> 6;        // 0..3, 16 cols each
        int gr  = bm + r;
        int sc  = selc[gr];
        float local = 0.f;
        #pragma unroll
        for (int cc = 0; cc < 16; cc++) {
            int c  = seg * 16 + cc;
            int gc = bn + c;
            if (gc < N) {
                float logit = Cs[r][c] + bias[gc];
                local += __expf(logit);           // logits are tiny: no max-sub needed
                if (gc == sc) selv[gr] = logit;
            }
        }
        rs[r][seg] = local;
        __syncthreads();
        if (seg == 0) {
            float tot = rs[r][0] + rs[r][1] + rs[r][2] + rs[r][3];
            atomicAdd(&sumexp[gr], tot);
        }
    }
}

// ---------------- cluster logits (head columns 20000, 20001) ----------------
__global__ void k_cluster(const __nv_bfloat16* __restrict__ hp0,
                          const float* __restrict__ cw,
                          const float* __restrict__ cb)
{
    int row  = blockIdx.x * 8 + (threadIdx.x >> 5);
    int lane = threadIdx.x & 31;
    if (row >= NROWS) return;
    float s0 = 0.f, s1 = 0.f;
    for (int k = lane; k < DIM; k += 32) {
        float h = __bfloat162float(hp0[(size_t)row * DIM + k]);
        s0 += h * cw[k];
        s1 += h * cw[DIM + k];
    }
    #pragma unroll
    for (int o = 16; o > 0; o >>= 1) {
        s0 += __shfl_xor_sync(0xffffffffu, s0, o);
        s1 += __shfl_xor_sync(0xffffffffu, s1, o);
    }
    if (lane == 0) {
        float c0 = s0 + cb[0];   // head column 20000 (cluster row 0)
        float c1 = s1 + cb[1];   // head column 20001 (cluster row 1)
        atomicAdd(&g_sum0[row], __expf(c0) + __expf(c1));
        int t = g_tgt[row];
        // reference quirk: tail i uses head_lp[:, -i]:
        //   tail1 (20000<=t<50000) -> col 20001 -> c1 ; tail2 (t>=50000) -> col 20000 -> c0
        if (t >= 50000)      g_selh[row] = c0;
        else if (t >= 20000) g_selh[row] = c1;
    }
}

// ---------------- finalize ----------------
__global__ void k_final(float* __restrict__ out) {
    int r = blockIdx.x * blockDim.x + threadIdx.x;
    if (r >= NROWS) return;
    int t = g_tgt[r];
    float lse0 = logf(g_sum0[r]);
    float nll;
    if (t < 20000)
        nll = -(g_selh[r] - lse0);
    else if (t < 50000)
        nll = -((g_selh[r] - lse0) + (g_selv1[r] - logf(g_sum1[r])));
    else
        nll = -((g_selh[r] - lse0) + (g_selv2[r] - logf(g_sum2[r])));
    out[r] = nll;
}

// ---------------- launch ----------------
static inline void* sym(const void* s) {
    void* p = nullptr;
    cudaGetSymbolAddress(&p, s);
    return p;
}

extern "C" void kernel_launch(void* const* d_in, const int* in_sizes, int n_in,
                              void* d_out, int out_size)
{
    const float* hidden = (const float*)d_in[0];
    const int*   target = (const int*)d_in[1];    // int32 or int64 — decoded on device
    const float* w0     = (const float*)d_in[2];
    const float* b0     = (const float*)d_in[3];
    const float* cw     = (const float*)d_in[4];
    const float* cb     = (const float*)d_in[5];
    const float* p0     = (const float*)d_in[6];
    const float* w1     = (const float*)d_in[7];
    const float* b1     = (const float*)d_in[8];
    const float* p1     = (const float*)d_in[9];
    const float* w2     = (const float*)d_in[10];
    const float* b2     = (const float*)d_in[11];
    const float* p2     = (const float*)d_in[12];
    float* out = (float*)d_out;

    __nv_bfloat16* h_bf   = (__nv_bfloat16*)sym(g_h_bf);
    __nv_bfloat16* p0_bf  = (__nv_bfloat16*)sym(g_p0_bf);
    __nv_bfloat16* p1_bf  = (__nv_bfloat16*)sym(g_p1_bf);
    __nv_bfloat16* p2_bf  = (__nv_bfloat16*)sym(g_p2_bf);
    __nv_bfloat16* w0_bf  = (__nv_bfloat16*)sym(g_w0_bf);
    __nv_bfloat16* w1_bf  = (__nv_bfloat16*)sym(g_w1_bf);
    __nv_bfloat16* w2_bf  = (__nv_bfloat16*)sym(g_w2_bf);
    float*         hp0_f  = (float*)sym(g_hp0_f);
    float*         hp1_f  = (float*)sym(g_hp1_f);
    float*         hp2_f  = (float*)sym(g_hp2_f);
    __nv_bfloat16* hp0_bf = (__nv_bfloat16*)sym(g_hp0_bf);
    __nv_bfloat16* hp1_bf = (__nv_bfloat16*)sym(g_hp1_bf);
    __nv_bfloat16* hp2_bf = (__nv_bfloat16*)sym(g_hp2_bf);
    float* sum0 = (float*)sym(g_sum0);
    float* sum1 = (float*)sym(g_sum1);
    float* sum2 = (float*)sym(g_sum2);
    float* selh  = (float*)sym(g_selh);
    float* selv1 = (float*)sym(g_selv1);
    float* selv2 = (float*)sym(g_selv2);
    int* selc0 = (int*)sym(g_selc0);
    int* selc1 = (int*)sym(g_selc1);
    int* selc2 = (int*)sym(g_selc2);

    // 1. decode targets (dtype-robust) + init accumulators
    k_init<<<1, 256>>>(target);

    // 2. fp32 -> bf16 conversions of inputs
    auto conv = [](__nv_bfloat16* d, const float* s, int n) {
        int g = (n + 255) / 256; if (g > 16384) g = 16384;
        k_conv<<<g, 256>>>(d, s, n);
    };
    conv(h_bf,  hidden, NROWS * DIM);
    conv(p0_bf, p0, 1024 * 1024);
    conv(p1_bf, p1, 1024 * 256);
    conv(p2_bf, p2, 1024 * 64);
    conv(w0_bf, w0, 20000 * 1024);
    conv(w1_bf, w1, 30000 * 256);
    conv(w2_bf, w2, 50000 * 64);

    // 3. projection GEMMs: hp = h @ proj  (NN layout, unfused)
    k_gemm<false, false><<<dim3(1024 / 64, NROWS / 64), 256>>>(
        h_bf, p0_bf, nullptr, hp0_f, 1024, 1024, nullptr, nullptr, nullptr);
    k_gemm<false, false><<<dim3(256 / 64, NROWS / 64), 256>>>(
        h_bf, p1_bf, nullptr, hp1_f, 256, 1024, nullptr, nullptr, nullptr);
    k_gemm<false, false><<<dim3(64 / 64, NROWS / 64), 256>>>(
        h_bf, p2_bf, nullptr, hp2_f, 64, 1024, nullptr, nullptr, nullptr);

    // 4. hp -> bf16
    conv(hp0_bf, hp0_f, NROWS * 1024);
    conv(hp1_bf, hp1_f, NROWS * 256);
    conv(hp2_bf, hp2_f, NROWS * 64);

    // 5. fused logit GEMMs: logits = hp @ W^T + b, accumulate exp-sums + capture target logit
    k_gemm<true, true><<<dim3((20000 + 63) / 64, NROWS / 64), 256>>>(
        hp0_bf, w0_bf, b0, nullptr, 20000, 1024, selc0, selh, sum0);
    k_gemm<true, true><<<dim3((30000 + 63) / 64, NROWS / 64), 256>>>(
        hp1_bf, w1_bf, b1, nullptr, 30000, 256, selc1, selv1, sum1);
    k_gemm<true, true><<<dim3((50000 + 63) / 64, NROWS / 64), 256>>>(
        hp2_bf, w2_bf, b2, nullptr, 50000, 64, selc2, selv2, sum2);

    // 6. cluster logits (head cols 20000, 20001)
    k_cluster<<<NROWS / 8, 256>>>(hp0_bf, cw, cb);

    // 7. finalize nll
    k_final<<<(NROWS + 255) / 256, 256>>>(out);
}

// round 4
// speedup vs baseline: 1.4080x; 1.4080x over previous
#include <cuda_runtime.h>
#include <cuda_bf16.h>
#include <mma.h>
#include <cstdint>

using namespace nvcuda;

#define NROWS 2048
#define DIM   1024

// ---------------- scratch (__device__ globals; no allocations allowed) ----------------
__device__ __align__(256) __nv_bfloat16 g_h_bf  [NROWS*DIM];
__device__ __align__(256) __nv_bfloat16 g_p0_bf [1024*1024];
__device__ __align__(256) __nv_bfloat16 g_p1_bf [1024*256];
__device__ __align__(256) __nv_bfloat16 g_p2_bf [1024*64];
__device__ __align__(256) __nv_bfloat16 g_w0_bf [20000*1024];
__device__ __align__(256) __nv_bfloat16 g_w1_bf [30000*256];
__device__ __align__(256) __nv_bfloat16 g_w2_bf [50000*64];
__device__ __align__(256) __nv_bfloat16 g_hp0_bf[NROWS*1024];
__device__ __align__(256) __nv_bfloat16 g_hp1_bf[NROWS*256];
__device__ __align__(256) __nv_bfloat16 g_hp2_bf[NROWS*64];
__device__ __align__(256) float g_sum0[NROWS];
__device__ __align__(256) float g_sum1[NROWS];
__device__ __align__(256) float g_sum2[NROWS];
__device__ __align__(256) float g_selh [NROWS];
__device__ __align__(256) float g_selv1[NROWS];
__device__ __align__(256) float g_selv2[NROWS];
__device__ __align__(256) int   g_selc0[NROWS];
__device__ __align__(256) int   g_selc1[NROWS];
__device__ __align__(256) int   g_selc2[NROWS];
__device__ __align__(256) int   g_tgt  [NROWS];

// ---------------- fp32 -> bf16 conversion (float4 vectorized) ----------------
__global__ void k_conv4(__nv_bfloat16* __restrict__ dst, const float* __restrict__ src, int n4) {
    int i = blockIdx.x * blockDim.x + threadIdx.x;
    int stride = gridDim.x * blockDim.x;
    const float4* s4 = reinterpret_cast<const float4*>(src);
    __nv_bfloat162* d2 = reinterpret_cast<__nv_bfloat162*>(dst);
    for (; i < n4; i += stride) {
        float4 v = s4[i];
        d2[2*i]   = __floats2bfloat162_rn(v.x, v.y);
        d2[2*i+1] = __floats2bfloat162_rn(v.z, v.w);
    }
}

// ---------------- init (single block): detect target dtype, decode, zero accumulators ----
__global__ void k_init(const int* __restrict__ t32) {
    __shared__ int s_nonzero_odd;
    if (threadIdx.x == 0) s_nonzero_odd = 0;
    __syncthreads();
    for (int i = threadIdx.x; i < NROWS / 2; i += blockDim.x)
        if (t32[2 * i + 1] != 0) atomicOr(&s_nonzero_odd, 1);
    __syncthreads();
    bool is64 = (s_nonzero_odd == 0);
    for (int r = threadIdx.x; r < NROWS; r += blockDim.x) {
        int t = is64 ? t32[2 * r] : t32[r];
        g_tgt[r] = t;
        g_sum0[r] = 0.f; g_sum1[r] = 0.f; g_sum2[r] = 0.f;
        g_selc0[r] = (t < 20000) ? t : -1;
        int t1 = t - 20000; if (t1 < 0) t1 = 0; if (t1 > 29999) t1 = 29999;
        g_selc1[r] = t1;
        int t2 = t - 50000; if (t2 < 0) t2 = 0; if (t2 > 49999) t2 = 49999;
        g_selc2[r] = t2;
    }
}

// ---------------- cp.async helpers ----------------
__device__ __forceinline__ void cpa16(void* smem_dst, const void* gsrc, int srcsize) {
    unsigned int d = (unsigned int)__cvta_generic_to_shared(smem_dst);
    asm volatile("cp.async.cg.shared.global [%0], [%1], 16, %2;\n"
                 :: "r"(d), "l"(gsrc), "r"(srcsize));
}
__device__ __forceinline__ void cpa_commit() { asm volatile("cp.async.commit_group;\n"); }
__device__ __forceinline__ void cpa_wait1()  { asm volatile("cp.async.wait_group 1;\n"); }
__device__ __forceinline__ void cpa_wait0()  { asm volatile("cp.async.wait_group 0;\n"); }

// ---------------- big-tile bf16 wmma GEMM, 2-stage cp.async pipeline ----------------
// Block tile 128x128, BK=32, 256 threads (8 warps, 4(m) x 2(n), warp tile 32x64).
//   BT=true : B is [N,K] row-major  -> C = A * B^T  (head/tail logits)
//   BT=false: B is [K,N] row-major  -> C = A * B    (projections)
// FUSE=true : epilogue computes exp(logit+bias) row-sums (atomicAdd) + captures
//             logit at selc[row] into selv[row]. Nothing stored to C.
// FUSE=false: epilogue writes C as bf16 (guarded for N < tile).
template<bool BT, bool FUSE>
__global__ void __launch_bounds__(256, 2)
k_gemm2(const __nv_bfloat16* __restrict__ A,
        const __nv_bfloat16* __restrict__ B,
        const float* __restrict__ bias,
        __nv_bfloat16* __restrict__ Cbf,
        int N, int K,
        const int* __restrict__ selc,
        float* __restrict__ selv,
        float* __restrict__ sumexp)
{
    constexpr int BM = 128, BN = 128, BK = 32;
    constexpr int SA  = BK + 8;    // 40 bf16 = 80B rows (16B aligned)
    constexpr int SBN = BN + 8;    // 136 bf16 = 272B rows (16B aligned)
    constexpr int STAGE_BYTES = 20480;   // A(10240) + B(10240)
    constexpr int CS_LD = 68;            // epilogue staging stride (floats)

    __shared__ __align__(128) char smem_raw[2 * STAGE_BYTES];   // 40 KB

    const int tid  = threadIdx.x;
    const int warp = tid >> 5;
    const int wm   = warp & 3;      // 0..3 -> rows wm*32
    const int wn   = warp >> 2;     // 0..1 -> cols wn*64
    const int bm   = blockIdx.y * BM;
    const int bn   = blockIdx.x * BN;

    auto As_of = [&](int s) { return reinterpret_cast<__nv_bfloat16*>(smem_raw + s * STAGE_BYTES); };
    auto Bs_of = [&](int s) { return reinterpret_cast<__nv_bfloat16*>(smem_raw + s * STAGE_BYTES + 10240); };

    wmma::fragment<wmma::accumulator, 16, 16, 16, float> acc[2][4];
    #pragma unroll
    for (int fm = 0; fm < 2; fm++)
        #pragma unroll
        for (int fn = 0; fn < 4; fn++)
            wmma::fill_fragment(acc[fm][fn], 0.f);

    auto load_tile = [&](int kt, int s) {
        int k0 = kt * BK;
        __nv_bfloat16* As = As_of(s);
        __nv_bfloat16* Bs = Bs_of(s);
        #pragma unroll
        for (int i = 0; i < 2; i++) {
            int idx = tid + i * 256;
            int row = idx >> 2, col = (idx & 3) * 8;
            cpa16(&As[row * SA + col], A + (size_t)(bm + row) * K + k0 + col, 16);
        }
        if constexpr (BT) {
            #pragma unroll
            for (int i = 0; i < 2; i++) {
                int idx = tid + i * 256;
                int row = idx >> 2, col = (idx & 3) * 8;
                int gn = bn + row;
                const __nv_bfloat16* src = B + (size_t)(gn < N ? gn : 0) * K + k0 + col;
                cpa16(&Bs[row * SA + col], src, (gn < N) ? 16 : 0);
            }
        } else {
            #pragma unroll
            for (int i = 0; i < 2; i++) {
                int idx = tid + i * 256;
                int row = idx >> 4, col = (idx & 15) * 8;   // 32 k-rows x 128 n-cols
                bool ok = (bn + col) < N;
                const __nv_bfloat16* src = B + (size_t)(k0 + row) * N + (ok ? bn + col : 0);
                cpa16(&Bs[row * SBN + col], src, ok ? 16 : 0);
            }
        }
    };

    const int KT = K / BK;
    load_tile(0, 0);
    cpa_commit();

    for (int kt = 0; kt < KT; kt++) {
        int s = kt & 1;
        if (kt + 1 < KT) { load_tile(kt + 1, s ^ 1); cpa_commit(); cpa_wait1(); }
        else             { cpa_wait0(); }
        __syncthreads();

        const __nv_bfloat16* As = As_of(s);
        const __nv_bfloat16* Bs = Bs_of(s);
        #pragma unroll
        for (int kk = 0; kk < BK; kk += 16) {
            wmma::fragment<wmma::matrix_a, 16, 16, 16, __nv_bfloat16, wmma::row_major> af[2];
            #pragma unroll
            for (int fm = 0; fm < 2; fm++)
                wmma::load_matrix_sync(af[fm], As + (wm * 32 + fm * 16) * SA + kk, SA);
            if constexpr (BT) {
                #pragma unroll
                for (int fn = 0; fn < 4; fn++) {
                    wmma::fragment<wmma::matrix_b, 16, 16, 16, __nv_bfloat16, wmma::col_major> bf;
                    wmma::load_matrix_sync(bf, Bs + (wn * 64 + fn * 16) * SA + kk, SA);
                    #pragma unroll
                    for (int fm = 0; fm < 2; fm++)
                        wmma::mma_sync(acc[fm][fn], af[fm], bf, acc[fm][fn]);
                }
            } else {
                #pragma unroll
                for (int fn = 0; fn < 4; fn++) {
                    wmma::fragment<wmma::matrix_b, 16, 16, 16, __nv_bfloat16, wmma::row_major> bf;
                    wmma::load_matrix_sync(bf, Bs + kk * SBN + wn * 64 + fn * 16, SBN);
                    #pragma unroll
                    for (int fm = 0; fm < 2; fm++)
                        wmma::mma_sync(acc[fm][fn], af[fm], bf, acc[fm][fn]);
                }
            }
        }
        __syncthreads();
    }

    // ---------------- epilogue: overlay staging buffer on pipeline SMEM ----------------
    float* Cs = reinterpret_cast<float*>(smem_raw);   // [128][68]

    const int r    = tid >> 1;          // 0..127 (row within tile)
    const int half = tid & 1;           // column half within 64-col pass
    const int gr   = bm + r;
    int   sc = 0;
    float rowsum = 0.f;
    if constexpr (FUSE) sc = selc[gr];

    #pragma unroll
    for (int pass = 0; pass < 2; pass++) {
        if (wn == pass) {
            #pragma unroll
            for (int fm = 0; fm < 2; fm++)
                #pragma unroll
                for (int fn = 0; fn < 4; fn++)
                    wmma::store_matrix_sync(&Cs[(wm * 32 + fm * 16) * CS_LD + fn * 16],
                                            acc[fm][fn], CS_LD, wmma::mem_row_major);
        }
        __syncthreads();

        #pragma unroll 8
        for (int c = 0; c < 32; c++) {
            int col = half * 32 + c;
            int gc  = bn + pass * 64 + col;
            if (gc < N) {
                float v = Cs[r * CS_LD + col];
                if constexpr (FUSE) {
                    float logit = v + __ldg(bias + gc);
                    rowsum += __expf(logit);
                    if (gc == sc) selv[gr] = logit;
                } else {
                    Cbf[(size_t)gr * N + gc] = __float2bfloat16(v);
                }
            }
        }
        __syncthreads();
    }

    if constexpr (FUSE) {
        rowsum += __shfl_xor_sync(0xffffffffu, rowsum, 1);
        if (half == 0) atomicAdd(&sumexp[gr], rowsum);
    }
}

// ---------------- cluster logits (head columns 20000, 20001) ----------------
__global__ void k_cluster(const __nv_bfloat16* __restrict__ hp0,
                          const float* __restrict__ cw,
                          const float* __restrict__ cb)
{
    int row  = blockIdx.x * 8 + (threadIdx.x >> 5);
    int lane = threadIdx.x & 31;
    if (row >= NROWS) return;
    float s0 = 0.f, s1 = 0.f;
    for (int k = lane; k < DIM; k += 32) {
        float h = __bfloat162float(hp0[(size_t)row * DIM + k]);
        s0 += h * cw[k];
        s1 += h * cw[DIM + k];
    }
    #pragma unroll
    for (int o = 16; o > 0; o >>= 1) {
        s0 += __shfl_xor_sync(0xffffffffu, s0, o);
        s1 += __shfl_xor_sync(0xffffffffu, s1, o);
    }
    if (lane == 0) {
        float c0 = s0 + cb[0];   // head column 20000 (cluster row 0)
        float c1 = s1 + cb[1];   // head column 20001 (cluster row 1)
        atomicAdd(&g_sum0[row], __expf(c0) + __expf(c1));
        int t = g_tgt[row];
        // reference quirk head_lp[:, -i]: tail1 -> col 20001 (c1); tail2 -> col 20000 (c0)
        if (t >= 50000)      g_selh[row] = c0;
        else if (t >= 20000) g_selh[row] = c1;
    }
}

// ---------------- finalize ----------------
__global__ void k_final(float* __restrict__ out) {
    int r = blockIdx.x * blockDim.x + threadIdx.x;
    if (r >= NROWS) return;
    int t = g_tgt[r];
    float lse0 = logf(g_sum0[r]);
    float nll;
    if (t < 20000)
        nll = -(g_selh[r] - lse0);
    else if (t < 50000)
        nll = -((g_selh[r] - lse0) + (g_selv1[r] - logf(g_sum1[r])));
    else
        nll = -((g_selh[r] - lse0) + (g_selv2[r] - logf(g_sum2[r])));
    out[r] = nll;
}

// ---------------- launch ----------------
static inline void* sym(const void* s) {
    void* p = nullptr;
    cudaGetSymbolAddress(&p, s);
    return p;
}

extern "C" void kernel_launch(void* const* d_in, const int* in_sizes, int n_in,
                              void* d_out, int out_size)
{
    const float* hidden = (const float*)d_in[0];
    const int*   target = (const int*)d_in[1];   // int32 or int64 — decoded on device
    const float* w0     = (const float*)d_in[2];
    const float* b0     = (const float*)d_in[3];
    const float* cw     = (const float*)d_in[4];
    const float* cb     = (const float*)d_in[5];
    const float* p0     = (const float*)d_in[6];
    const float* w1     = (const float*)d_in[7];
    const float* b1     = (const float*)d_in[8];
    const float* p1     = (const float*)d_in[9];
    const float* w2     = (const float*)d_in[10];
    const float* b2     = (const float*)d_in[11];
    const float* p2     = (const float*)d_in[12];
    float* out = (float*)d_out;

    __nv_bfloat16* h_bf   = (__nv_bfloat16*)sym(g_h_bf);
    __nv_bfloat16* p0_bf  = (__nv_bfloat16*)sym(g_p0_bf);
    __nv_bfloat16* p1_bf  = (__nv_bfloat16*)sym(g_p1_bf);
    __nv_bfloat16* p2_bf  = (__nv_bfloat16*)sym(g_p2_bf);
    __nv_bfloat16* w0_bf  = (__nv_bfloat16*)sym(g_w0_bf);
    __nv_bfloat16* w1_bf  = (__nv_bfloat16*)sym(g_w1_bf);
    __nv_bfloat16* w2_bf  = (__nv_bfloat16*)sym(g_w2_bf);
    __nv_bfloat16* hp0_bf = (__nv_bfloat16*)sym(g_hp0_bf);
    __nv_bfloat16* hp1_bf = (__nv_bfloat16*)sym(g_hp1_bf);
    __nv_bfloat16* hp2_bf = (__nv_bfloat16*)sym(g_hp2_bf);
    float* sum0 = (float*)sym(g_sum0);
    float* sum1 = (float*)sym(g_sum1);
    float* sum2 = (float*)sym(g_sum2);
    float* selh  = (float*)sym(g_selh);
    float* selv1 = (float*)sym(g_selv1);
    float* selv2 = (float*)sym(g_selv2);
    int* selc0 = (int*)sym(g_selc0);
    int* selc1 = (int*)sym(g_selc1);
    int* selc2 = (int*)sym(g_selc2);

    // 1. decode targets + init accumulators
    k_init<<<1, 256>>>(target);

    // 2. fp32 -> bf16 conversions
    auto conv = [](__nv_bfloat16* d, const float* s, int n) {
        int n4 = n / 4;
        int g = (n4 + 255) / 256; if (g > 4096) g = 4096;
        k_conv4<<<g, 256>>>(d, s, n4);
    };
    conv(h_bf,  hidden, NROWS * DIM);
    conv(p0_bf, p0, 1024 * 1024);
    conv(p1_bf, p1, 1024 * 256);
    conv(p2_bf, p2, 1024 * 64);
    conv(w0_bf, w0, 20000 * 1024);
    conv(w1_bf, w1, 30000 * 256);
    conv(w2_bf, w2, 50000 * 64);

    // 3. projection GEMMs: hp = h @ proj (bf16 out, conversion fused)
    k_gemm2<false, false><<<dim3(1024 / 128, NROWS / 128), 256>>>(
        h_bf, p0_bf, nullptr, hp0_bf, 1024, 1024, nullptr, nullptr, nullptr);
    k_gemm2<false, false><<<dim3(2, NROWS / 128), 256>>>(
        h_bf, p1_bf, nullptr, hp1_bf, 256, 1024, nullptr, nullptr, nullptr);
    k_gemm2<false, false><<<dim3(1, NROWS / 128), 256>>>(
        h_bf, p2_bf, nullptr, hp2_bf, 64, 1024, nullptr, nullptr, nullptr);

    // 4. fused logit GEMMs: exp-sums + target-logit capture
    k_gemm2<true, true><<<dim3((20000 + 127) / 128, NROWS / 128), 256>>>(
        hp0_bf, w0_bf, b0, nullptr, 20000, 1024, selc0, selh, sum0);
    k_gemm2<true, true><<<dim3((30000 + 127) / 128, NROWS / 128), 256>>>(
        hp1_bf, w1_bf, b1, nullptr, 30000, 256, selc1, selv1, sum1);
    k_gemm2<true, true><<<dim3((50000 + 127) / 128, NROWS / 128), 256>>>(
        hp2_bf, w2_bf, b2, nullptr, 50000, 64, selc2, selv2, sum2);

    // 5. cluster logits (head cols 20000, 20001)
    k_cluster<<<NROWS / 8, 256>>>(hp0_bf, cw, cb);

    // 6. finalize nll
    k_final<<<(NROWS + 255) / 256, 256>>>(out);
}

// round 6
// speedup vs baseline: 1.7610x; 1.2507x over previous
#include <cuda_runtime.h>
#include <cuda_bf16.h>
#include <mma.h>
#include <cstdint>

using namespace nvcuda;

#define NROWS 2048
#define DIM   1024

// Packed slab layout: matrix [Rpad, K] (K-major) stored as slabs of 128 rows x 64 K.
// Slab (rt, kt) at element offset ((rt*(K/64))+kt)*9216; within slab row r at r*72,
// col c at +c. 72-elem (144B) row stride = bank-conflict-safe padding; slab = 18432B
// contiguous in gmem -> one cp.async.bulk per slab.
#define SLAB_ELEMS 9216
#define SLAB_BYTES 18432

// ================= helpers =================
__device__ __forceinline__ uint32_t smem_u32(const void* p) {
    uint32_t a;
    asm("{ .reg .u64 t; cvta.to.shared.u64 t, %1; cvt.u32.u64 %0, t; }" : "=r"(a) : "l"(p));
    return a;
}
#define MBARRIER_INIT(mbar, cnt) \
    asm volatile("mbarrier.init.shared.b64 [%0], %1;" \
                 :: "r"((uint32_t)(mbar)), "r"((uint32_t)(cnt)) : "memory")
#define MBARRIER_EXPECT_TX(mbar, tx) \
    asm volatile("mbarrier.arrive.expect_tx.shared.b64 _, [%0], %1;" \
                 :: "r"((uint32_t)(mbar)), "r"((uint32_t)(tx)) : "memory")
#define MBARRIER_WAIT_PARITY(mbar, par) do { \
    uint32_t _m = (uint32_t)(mbar); uint32_t _p = (uint32_t)(par); uint32_t _d; \
    asm volatile("{\n\t.reg .pred p;\n\t" \
        "mbarrier.try_wait.parity.acquire.cta.shared::cta.b64 p, [%1], %2;\n\t" \
        "selp.b32 %0, 1, 0, p;\n\t}" : "=r"(_d) : "r"(_m), "r"(_p) : "memory"); \
    if (!_d) { \
        asm volatile("{\n\t.reg .pred P1;\n\t" \
            "WL_%=:\n\t" \
            "mbarrier.try_wait.parity.acquire.cta.shared::cta.b64 P1, [%0], %1, 0x989680;\n\t" \
            "@P1 bra.uni WD_%=;\n\t" \
            "bra.uni WL_%=;\n\t" \
            "WD_%=:\n\t}" :: "r"(_m), "r"(_p) : "memory"); \
    } \
} while (0)
__device__ __forceinline__ void bulk_g2s(uint32_t dst, const void* src, uint32_t bytes,
                                         uint32_t mbar) {
    asm volatile(
        "cp.async.bulk.shared::cluster.global.mbarrier::complete_tx::bytes [%0], [%1], %2, [%3];"
        :: "r"(dst), "l"(src), "r"(bytes), "r"(mbar) : "memory");
}

// ================= packed scratch buffers (bf16) =================
__device__ __align__(256) __nv_bfloat16 g_hP  [16 * 16 * SLAB_ELEMS];   // h    [2048,1024]
__device__ __align__(256) __nv_bfloat16 g_p0T [ 8 * 16 * SLAB_ELEMS];   // p0^T [1024,1024]
__device__ __align__(256) __nv_bfloat16 g_p1T [ 2 * 16 * SLAB_ELEMS];   // p1^T [256, 1024]
__device__ __align__(256) __nv_bfloat16 g_p2T [ 1 * 16 * SLAB_ELEMS];   // p2^T [64->128,1024]
__device__ __align__(256) __nv_bfloat16 g_w0P [157 * 16 * SLAB_ELEMS];  // w0 [20000->20096,1024]
__device__ __align__(256) __nv_bfloat16 g_w1P [235 *  4 * SLAB_ELEMS];  // w1 [30000->30080,256]
__device__ __align__(256) __nv_bfloat16 g_w2P [391 *  1 * SLAB_ELEMS];  // w2 [50000->50048,64]
__device__ __align__(256) __nv_bfloat16 g_hp0P[16 * 16 * SLAB_ELEMS];   // hp0 [2048,1024]
__device__ __align__(256) __nv_bfloat16 g_hp1P[16 *  4 * SLAB_ELEMS];   // hp1 [2048,256]
__device__ __align__(256) __nv_bfloat16 g_hp2P[16 *  1 * SLAB_ELEMS];   // hp2 [2048,64]
__device__ __align__(256) float g_sum0[NROWS];
__device__ __align__(256) float g_sum1[NROWS];
__device__ __align__(256) float g_sum2[NROWS];
__device__ __align__(256) float g_selh [NROWS];
__device__ __align__(256) float g_selv1[NROWS];
__device__ __align__(256) float g_selv2[NROWS];
__device__ __align__(256) int   g_selc0[NROWS];
__device__ __align__(256) int   g_selc1[NROWS];
__device__ __align__(256) int   g_selc2[NROWS];
__device__ __align__(256) int   g_tgt  [NROWS];

// ================= pack: fp32 [R,K] row-major -> packed bf16 slabs, zero-pad to Rpad ======
__global__ void k_pack(__nv_bfloat16* __restrict__ dst, const float* __restrict__ src,
                       int R, int Rpad, int K) {
    int total = Rpad * (K >> 3);   // 8-elem chunks
    int stride = gridDim.x * blockDim.x;
    for (int idx = blockIdx.x * blockDim.x + threadIdx.x; idx < total; idx += stride) {
        int r = idx / (K >> 3);
        int c = idx - r * (K >> 3);        // 16B chunk index within row
        int kt = c >> 3, ci = c & 7;
        size_t doff = ((size_t)(r >> 7) * (K >> 6) + kt) * SLAB_ELEMS
                      + (size_t)(r & 127) * 72 + ci * 8;
        uint4 o = make_uint4(0u, 0u, 0u, 0u);
        if (r < R) {
            const float4* s = reinterpret_cast<const float4*>(src + (size_t)r * K + c * 8);
            float4 v0 = s[0], v1 = s[1];
            __nv_bfloat162 b0 = __floats2bfloat162_rn(v0.x, v0.y);
            __nv_bfloat162 b1 = __floats2bfloat162_rn(v0.z, v0.w);
            __nv_bfloat162 b2 = __floats2bfloat162_rn(v1.x, v1.y);
            __nv_bfloat162 b3 = __floats2bfloat162_rn(v1.z, v1.w);
            o.x = *reinterpret_cast<uint32_t*>(&b0);
            o.y = *reinterpret_cast<uint32_t*>(&b1);
            o.z = *reinterpret_cast<uint32_t*>(&b2);
            o.w = *reinterpret_cast<uint32_t*>(&b3);
        }
        *reinterpret_cast<uint4*>(dst + doff) = o;
    }
}

// ================= transpose-pack: fp32 src [K,N] -> packed bf16 [Npad,K] =================
__global__ void k_packT(__nv_bfloat16* __restrict__ dst, const float* __restrict__ src,
                        int K, int N) {
    __shared__ float t[32][33];
    int n0 = blockIdx.x * 32, k0 = blockIdx.y * 32;
    int x = threadIdx.x, y = threadIdx.y;   // 32 x 8
    #pragma unroll
    for (int i = 0; i < 32; i += 8)
        t[y + i][x] = (n0 + x < N) ? src[(size_t)(k0 + y + i) * N + n0 + x] : 0.f;
    __syncthreads();
    #pragma unroll
    for (int i = 0; i < 32; i += 8) {
        int n = n0 + y + i, k = k0 + x;
        size_t doff = ((size_t)(n >> 7) * (K >> 6) + (k >> 6)) * SLAB_ELEMS
                      + (size_t)(n & 127) * 72 + (k & 63);
        dst[doff] = __float2bfloat16(t[x][y + i]);
    }
}

// ================= init: decode targets (int32 OR int64), zero accumulators ==============
__global__ void k_init(const int* __restrict__ t32) {
    __shared__ int s_nonzero_odd;
    if (threadIdx.x == 0) s_nonzero_odd = 0;
    __syncthreads();
    for (int i = threadIdx.x; i < NROWS / 2; i += blockDim.x)
        if (t32[2 * i + 1] != 0) atomicOr(&s_nonzero_odd, 1);
    __syncthreads();
    bool is64 = (s_nonzero_odd == 0);
    for (int r = threadIdx.x; r < NROWS; r += blockDim.x) {
        int t = is64 ? t32[2 * r] : t32[r];
        g_tgt[r] = t;
        g_sum0[r] = 0.f; g_sum1[r] = 0.f; g_sum2[r] = 0.f;
        g_selc0[r] = (t < 20000) ? t : -1;
        int t1 = t - 20000; if (t1 < 0) t1 = 0; if (t1 > 29999) t1 = 29999;
        g_selc1[r] = t1;
        int t2 = t - 50000; if (t2 < 0) t2 = 0; if (t2 > 49999) t2 = 49999;
        g_selc2[r] = t2;
    }
}

// ================= wmma GEMM over packed slabs, bulk-copy double-buffered =================
// C[2048,N] = A[2048,K] @ B[N,K]^T ; A, B packed. 128x128 tile, BK=64, 256 thr, 8 warps.
// FUSE=true : epilogue adds bias, per-row exp-sums (atomicAdd), captures logit at selc[row].
// FUSE=false: epilogue writes C bf16 in packed layout (C's K dim = N).
template<bool FUSE>
__global__ void __launch_bounds__(256, 2)
k_wm(const __nv_bfloat16* __restrict__ A,
     const __nv_bfloat16* __restrict__ B,
     const float* __restrict__ bias,
     __nv_bfloat16* __restrict__ Cp,
     int N, int K,
     const int* __restrict__ selc,
     float* __restrict__ selv,
     float* __restrict__ sumexp)
{
    extern __shared__ __align__(128) char dsm[];
    const uint32_t sb = smem_u32(dsm);        // mbarriers at +0, +8
    float* biasS = reinterpret_cast<float*>(dsm + 64);

    const int tid  = threadIdx.x;
    const int warp = tid >> 5;
    const int wm   = warp & 3;     // 0..3 -> rows wm*32
    const int wn   = warp >> 2;    // 0..1 -> cols wn*64
    const int bm   = blockIdx.y * 128;
    const int bn   = blockIdx.x * 128;
    const int KT   = K >> 6;

    auto slabA = [&](int s) {
        return reinterpret_cast<const __nv_bfloat16*>(dsm + 1024 + s * 2 * SLAB_BYTES);
    };
    auto slabB = [&](int s) {
        return reinterpret_cast<const __nv_bfloat16*>(dsm + 1024 + s * 2 * SLAB_BYTES + SLAB_BYTES);
    };

    if (tid == 0) { MBARRIER_INIT(sb, 1); MBARRIER_INIT(sb + 8, 1); }
    if (FUSE && tid < 128) {
        int gc = bn + tid;
        biasS[tid] = (gc < N) ? bias[gc] : 0.f;
    }
    __syncthreads();

    auto issue = [&](int kt, int s) {
        uint32_t mb = sb + (uint32_t)s * 8;
        MBARRIER_EXPECT_TX(mb, 2 * SLAB_BYTES);
        const char* aS = reinterpret_cast<const char*>(A)
                         + ((size_t)blockIdx.y * KT + kt) * SLAB_BYTES;
        const char* bS = reinterpret_cast<const char*>(B)
                         + ((size_t)blockIdx.x * KT + kt) * SLAB_BYTES;
        bulk_g2s(smem_u32(slabA(s)), aS, SLAB_BYTES, mb);
        bulk_g2s(smem_u32(slabB(s)), bS, SLAB_BYTES, mb);
    };
    if (tid == 0) { issue(0, 0); if (KT > 1) issue(1, 1); }

    wmma::fragment<wmma::accumulator, 16, 16, 16, float> acc[2][4];
    #pragma unroll
    for (int fm = 0; fm < 2; fm++)
        #pragma unroll
        for (int fn = 0; fn < 4; fn++)
            wmma::fill_fragment(acc[fm][fn], 0.f);

    for (int kt = 0; kt < KT; kt++) {
        int s = kt & 1;
        MBARRIER_WAIT_PARITY(sb + (uint32_t)s * 8, (kt >> 1) & 1);

        const __nv_bfloat16* As = slabA(s);
        const __nv_bfloat16* Bs = slabB(s);
        #pragma unroll
        for (int kk = 0; kk < 64; kk += 16) {
            wmma::fragment<wmma::matrix_a, 16, 16, 16, __nv_bfloat16, wmma::row_major> af[2];
            #pragma unroll
            for (int fm = 0; fm < 2; fm++)
                wmma::load_matrix_sync(af[fm], As + (wm * 32 + fm * 16) * 72 + kk, 72);
            #pragma unroll
            for (int fn = 0; fn < 4; fn++) {
                wmma::fragment<wmma::matrix_b, 16, 16, 16, __nv_bfloat16, wmma::col_major> bf;
                wmma::load_matrix_sync(bf, Bs + (wn * 64 + fn * 16) * 72 + kk, 72);
                #pragma unroll
                for (int fm = 0; fm < 2; fm++)
                    wmma::mma_sync(acc[fm][fn], af[fm], bf, acc[fm][fn]);
            }
        }
        __syncthreads();                       // all warps done reading slab s
        if (kt + 2 < KT && tid == 0) issue(kt + 2, s);
    }

    // -------- epilogue: overlay fp32 staging on slab smem (2 column passes of 64) --------
    float* Cs = reinterpret_cast<float*>(dsm + 1024);   // [128][68]
    const int r    = tid >> 1;
    const int half = tid & 1;
    const int gr   = bm + r;
    int   sc = 0;
    float rowsum = 0.f;
    if constexpr (FUSE) sc = selc[gr];

    #pragma unroll
    for (int pass = 0; pass < 2; pass++) {
        if (wn == pass) {
            #pragma unroll
            for (int fm = 0; fm < 2; fm++)
                #pragma unroll
                for (int fn = 0; fn < 4; fn++)
                    wmma::store_matrix_sync(&Cs[(wm * 32 + fm * 16) * 68 + fn * 16],
                                            acc[fm][fn], 68, wmma::mem_row_major);
        }
        __syncthreads();

        #pragma unroll 8
        for (int cc = 0; cc < 32; cc++) {
            int col    = half * 32 + cc;
            int col128 = pass * 64 + col;
            int gc     = bn + col128;
            float v = Cs[r * 68 + col];
            if constexpr (FUSE) {
                if (gc < N) {
                    float lg = v + biasS[col128];
                    rowsum += __expf(lg);
                    if (gc == sc) selv[gr] = lg;
                }
            } else {
                if (gc < N) {
                    size_t doff = ((size_t)(gr >> 7) * (N >> 6) + (gc >> 6)) * SLAB_ELEMS
                                  + (size_t)(gr & 127) * 72 + (gc & 63);
                    Cp[doff] = __float2bfloat16(v);
                }
            }
        }
        __syncthreads();
    }

    if constexpr (FUSE) {
        rowsum += __shfl_xor_sync(0xffffffffu, rowsum, 1);
        if (half == 0) atomicAdd(&sumexp[gr], rowsum);
    }
}

// ================= cluster logits (head cols 20000, 20001); hp0 is packed =================
__global__ void k_cluster(const __nv_bfloat16* __restrict__ hp0p,
                          const float* __restrict__ cw,
                          const float* __restrict__ cb)
{
    int row  = blockIdx.x * 8 + (threadIdx.x >> 5);
    int lane = threadIdx.x & 31;
    if (row >= NROWS) return;
    size_t rbase = (size_t)(row >> 7) * 16 * SLAB_ELEMS + (size_t)(row & 127) * 72;
    float s0 = 0.f, s1 = 0.f;
    for (int k = lane; k < DIM; k += 32) {
        float h = __bfloat162float(hp0p[rbase + (size_t)(k >> 6) * SLAB_ELEMS + (k & 63)]);
        s0 += h * cw[k];
        s1 += h * cw[DIM + k];
    }
    #pragma unroll
    for (int o = 16; o > 0; o >>= 1) {
        s0 += __shfl_xor_sync(0xffffffffu, s0, o);
        s1 += __shfl_xor_sync(0xffffffffu, s1, o);
    }
    if (lane == 0) {
        float c0 = s0 + cb[0];
        float c1 = s1 + cb[1];
        atomicAdd(&g_sum0[row], __expf(c0) + __expf(c1));
        int t = g_tgt[row];
        // reference quirk head_lp[:, -i]: tail1 -> col 20001 (c1); tail2 -> col 20000 (c0)
        if (t >= 50000)      g_selh[row] = c0;
        else if (t >= 20000) g_selh[row] = c1;
    }
}

// ================= finalize =================
__global__ void k_final(float* __restrict__ out) {
    int r = blockIdx.x * blockDim.x + threadIdx.x;
    if (r >= NROWS) return;
    int t = g_tgt[r];
    float lse0 = logf(g_sum0[r]);
    float nll;
    if (t < 20000)
        nll = -(g_selh[r] - lse0);
    else if (t < 50000)
        nll = -((g_selh[r] - lse0) + (g_selv1[r] - logf(g_sum1[r])));
    else
        nll = -((g_selh[r] - lse0) + (g_selv2[r] - logf(g_sum2[r])));
    out[r] = nll;
}

// ================= launch =================
static inline void* sym(const void* s) {
    void* p = nullptr;
    cudaGetSymbolAddress(&p, s);
    return p;
}

extern "C" void kernel_launch(void* const* d_in, const int* in_sizes, int n_in,
                              void* d_out, int out_size)
{
    const float* hidden = (const float*)d_in[0];
    const int*   target = (const int*)d_in[1];
    const float* w0     = (const float*)d_in[2];
    const float* b0     = (const float*)d_in[3];
    const float* cw     = (const float*)d_in[4];
    const float* cb     = (const float*)d_in[5];
    const float* p0     = (const float*)d_in[6];
    const float* w1     = (const float*)d_in[7];
    const float* b1     = (const float*)d_in[8];
    const float* p1     = (const float*)d_in[9];
    const float* w2     = (const float*)d_in[10];
    const float* b2     = (const float*)d_in[11];
    const float* p2     = (const float*)d_in[12];
    float* out = (float*)d_out;

    __nv_bfloat16* hP   = (__nv_bfloat16*)sym(g_hP);
    __nv_bfloat16* p0T  = (__nv_bfloat16*)sym(g_p0T);
    __nv_bfloat16* p1T  = (__nv_bfloat16*)sym(g_p1T);
    __nv_bfloat16* p2T  = (__nv_bfloat16*)sym(g_p2T);
    __nv_bfloat16* w0P  = (__nv_bfloat16*)sym(g_w0P);
    __nv_bfloat16* w1P  = (__nv_bfloat16*)sym(g_w1P);
    __nv_bfloat16* w2P  = (__nv_bfloat16*)sym(g_w2P);
    __nv_bfloat16* hp0P = (__nv_bfloat16*)sym(g_hp0P);
    __nv_bfloat16* hp1P = (__nv_bfloat16*)sym(g_hp1P);
    __nv_bfloat16* hp2P = (__nv_bfloat16*)sym(g_hp2P);
    float* sum0 = (float*)sym(g_sum0);
    float* sum1 = (float*)sym(g_sum1);
    float* sum2 = (float*)sym(g_sum2);
    float* selh  = (float*)sym(g_selh);
    float* selv1 = (float*)sym(g_selv1);
    float* selv2 = (float*)sym(g_selv2);
    int* selc0 = (int*)sym(g_selc0);
    int* selc1 = (int*)sym(g_selc1);
    int* selc2 = (int*)sym(g_selc2);

    const int SMEM_WM = 1024 + 4 * SLAB_BYTES;   // 74752
    cudaFuncSetAttribute(k_wm<true>,  cudaFuncAttributeMaxDynamicSharedMemorySize, SMEM_WM);
    cudaFuncSetAttribute(k_wm<false>, cudaFuncAttributeMaxDynamicSharedMemorySize, SMEM_WM);

    // 1. decode targets + init accumulators
    k_init<<<1, 256>>>(target);

    // 2. pack conversions (fp32 -> bf16 slabs)
    k_pack<<<1024, 256>>>(hP,  hidden, 2048,  2048,  1024);
    k_pack<<<4096, 256>>>(w0P, w0,     20000, 20096, 1024);
    k_pack<<<2048, 256>>>(w1P, w1,     30000, 30080, 256);
    k_pack<<<1024, 256>>>(w2P, w2,     50000, 50048, 64);
    k_packT<<<dim3(1024 / 32, 1024 / 32), dim3(32, 8)>>>(p0T, p0, 1024, 1024);
    k_packT<<<dim3(256 / 32,  1024 / 32), dim3(32, 8)>>>(p1T, p1, 1024, 256);
    k_packT<<<dim3(128 / 32,  1024 / 32), dim3(32, 8)>>>(p2T, p2, 1024, 64);  // pad to 128 rows

    // 3. projection GEMMs: hp = h @ proj (packed bf16 out)
    k_wm<false><<<dim3(8, 16), 256, SMEM_WM>>>(hP, p0T, nullptr, hp0P, 1024, 1024,
                                               nullptr, nullptr, nullptr);
    k_wm<false><<<dim3(2, 16), 256, SMEM_WM>>>(hP, p1T, nullptr, hp1P, 256, 1024,
                                               nullptr, nullptr, nullptr);
    k_wm<false><<<dim3(1, 16), 256, SMEM_WM>>>(hP, p2T, nullptr, hp2P, 64, 1024,
                                               nullptr, nullptr, nullptr);

    // 4. fused logit GEMMs: exp-sums + target-logit capture
    k_wm<true><<<dim3(157, 16), 256, SMEM_WM>>>(hp0P, w0P, b0, nullptr, 20000, 1024,
                                                selc0, selh, sum0);
    k_wm<true><<<dim3(235, 16), 256, SMEM_WM>>>(hp1P, w1P, b1, nullptr, 30000, 256,
                                                selc1, selv1, sum1);
    k_wm<true><<<dim3(391, 16), 256, SMEM_WM>>>(hp2P, w2P, b2, nullptr, 50000, 64,
                                                selc2, selv2, sum2);

    // 5. cluster logits
    k_cluster<<<NROWS / 8, 256>>>(hp0P, cw, cb);

    // 6. finalize
    k_final<<<(NROWS + 255) / 256, 256>>>(out);
}